// round 1
// baseline (speedup 1.0000x reference)
#include <cuda_runtime.h>

#define BATCH 8
#define SEQ   2048
#define CDIM  1024
#define HDIM  64
#define BT    (BATCH*SEQ)

// Scratch for projected q,k,v (device globals: no allocation allowed)
__device__ float g_q[BT*HDIM];
__device__ float g_k[BT*HDIM];
__device__ float g_v[BT*HDIM];

// ---------------------------------------------------------------------------
// Fused QKV projection: q|k|v = x @ Wq|Wk|Wv
// x: [BT, 1024], W*: [1024, 64]. Block computes 64 rows x (3x64) cols.
// Microtile per thread: 3 matrices x 4 rows x 4 cols.
// ---------------------------------------------------------------------------
__global__ __launch_bounds__(256, 2) void proj_kernel(
    const float* __restrict__ x,
    const float* __restrict__ Wk,
    const float* __restrict__ Wq,
    const float* __restrict__ Wv)
{
    __shared__ float xs[64][20];    // [row][k-chunk of 16], pad 20 (16B-aligned rows)
    __shared__ float ws[16][196];   // [k][3*64], pad 196 (16B-aligned rows)

    const int tid  = threadIdx.x;
    const int tr   = tid >> 4;      // 0..15 -> rows tr*4..tr*4+3
    const int tc   = tid & 15;      // 0..15 -> cols tc*4..tc*4+3 (per matrix)
    const int row0 = blockIdx.x * 64;

    const int lrow = tid >> 2;      // x-tile load: row 0..63
    const int lkq  = tid & 3;       // x-tile load: k-quad 0..3
    const int wkk  = tid >> 4;      // w-tile load: k 0..15
    const int wc4  = tid & 15;      // w-tile load: col-quad 0..15

    float acc[3][4][4];
    #pragma unroll
    for (int m = 0; m < 3; ++m)
        #pragma unroll
        for (int i = 0; i < 4; ++i)
            #pragma unroll
            for (int j = 0; j < 4; ++j) acc[m][i][j] = 0.f;

    for (int kc = 0; kc < CDIM; kc += 16) {
        // stage x tile [64][16]
        float4 xv = *(const float4*)(x + (size_t)(row0 + lrow)*CDIM + kc + lkq*4);
        *(float4*)&xs[lrow][lkq*4] = xv;
        // stage W tiles [16][64] x3  (m: 0=k, 1=q, 2=v)
        {
            float4 wv;
            wv = *(const float4*)(Wk + (size_t)(kc + wkk)*HDIM + wc4*4);
            *(float4*)&ws[wkk][0*64 + wc4*4] = wv;
            wv = *(const float4*)(Wq + (size_t)(kc + wkk)*HDIM + wc4*4);
            *(float4*)&ws[wkk][1*64 + wc4*4] = wv;
            wv = *(const float4*)(Wv + (size_t)(kc + wkk)*HDIM + wc4*4);
            *(float4*)&ws[wkk][2*64 + wc4*4] = wv;
        }
        __syncthreads();

        #pragma unroll
        for (int k4 = 0; k4 < 4; ++k4) {
            float4 a4[4];
            #pragma unroll
            for (int i = 0; i < 4; ++i)
                a4[i] = *(const float4*)&xs[tr*4 + i][k4*4];
            #pragma unroll
            for (int m = 0; m < 3; ++m) {
                float4 b0 = *(const float4*)&ws[k4*4 + 0][m*64 + tc*4];
                float4 b1 = *(const float4*)&ws[k4*4 + 1][m*64 + tc*4];
                float4 b2 = *(const float4*)&ws[k4*4 + 2][m*64 + tc*4];
                float4 b3 = *(const float4*)&ws[k4*4 + 3][m*64 + tc*4];
                #pragma unroll
                for (int i = 0; i < 4; ++i) {
                    acc[m][i][0] += a4[i].x*b0.x + a4[i].y*b1.x + a4[i].z*b2.x + a4[i].w*b3.x;
                    acc[m][i][1] += a4[i].x*b0.y + a4[i].y*b1.y + a4[i].z*b2.y + a4[i].w*b3.y;
                    acc[m][i][2] += a4[i].x*b0.z + a4[i].y*b1.z + a4[i].z*b2.z + a4[i].w*b3.z;
                    acc[m][i][3] += a4[i].x*b0.w + a4[i].y*b1.w + a4[i].z*b2.w + a4[i].w*b3.w;
                }
            }
        }
        __syncthreads();
    }

    #pragma unroll
    for (int i = 0; i < 4; ++i) {
        const size_t row = (size_t)(row0 + tr*4 + i);
        *(float4*)(g_k + row*HDIM + tc*4) =
            make_float4(acc[0][i][0], acc[0][i][1], acc[0][i][2], acc[0][i][3]);
        *(float4*)(g_q + row*HDIM + tc*4) =
            make_float4(acc[1][i][0], acc[1][i][1], acc[1][i][2], acc[1][i][3]);
        *(float4*)(g_v + row*HDIM + tc*4) =
            make_float4(acc[2][i][0], acc[2][i][1], acc[2][i][2], acc[2][i][3]);
    }
}

// ---------------------------------------------------------------------------
// Flash attention: per block = (batch b, 64 query rows). Online softmax over
// 32 key tiles of 64. Thread microtile 4 q-rows x 4 (key or head) cols.
// All SMEM rows padded to 68 floats: 16B-aligned + conflict-free float4 LDS.
// ---------------------------------------------------------------------------
__global__ __launch_bounds__(256, 2) void attn_kernel(float* __restrict__ out)
{
    extern __shared__ float sm[];
    float (*Qs)[68] = (float(*)[68])(sm);
    float (*Ks)[68] = (float(*)[68])(sm + 64*68);
    float (*Vs)[68] = (float(*)[68])(sm + 2*64*68);
    float (*Ps)[68] = (float(*)[68])(sm + 3*64*68);

    const int tid = threadIdx.x;
    const int tr  = tid >> 4;        // q-row group
    const int tc  = tid & 15;        // col group
    const int b   = blockIdx.y;
    const int q0  = blockIdx.x * 64;
    const float scale = 0.03125f;    // 1024^-0.5

    // Load + pre-scale Q tile [64][64]
    const float* qg = g_q + ((size_t)b*SEQ + q0)*HDIM;
    #pragma unroll
    for (int it = 0; it < 4; ++it) {
        int idx = tid + it*256;
        int row = idx >> 4, c4 = idx & 15;
        float4 v = *(const float4*)(qg + row*HDIM + c4*4);
        v.x *= scale; v.y *= scale; v.z *= scale; v.w *= scale;
        *(float4*)&Qs[row][c4*4] = v;
    }

    float m_i[4], l_i[4], o[4][4];
    #pragma unroll
    for (int i = 0; i < 4; ++i) {
        m_i[i] = -1e30f; l_i[i] = 0.f;
        o[i][0] = o[i][1] = o[i][2] = o[i][3] = 0.f;
    }

    for (int kt = 0; kt < SEQ; kt += 64) {
        const float* kg = g_k + ((size_t)b*SEQ + kt)*HDIM;
        const float* vg = g_v + ((size_t)b*SEQ + kt)*HDIM;

        __syncthreads();  // previous PV (and first-iter Q store ordering) done
        #pragma unroll
        for (int it = 0; it < 4; ++it) {
            int idx = tid + it*256;
            int row = idx >> 4, c4 = idx & 15;
            *(float4*)&Ks[row][c4*4] = *(const float4*)(kg + row*HDIM + c4*4);
            *(float4*)&Vs[row][c4*4] = *(const float4*)(vg + row*HDIM + c4*4);
        }
        __syncthreads();

        // S = (Q*scale) @ K^T, 4x4 per thread
        float s[4][4];
        #pragma unroll
        for (int i = 0; i < 4; ++i)
            s[i][0] = s[i][1] = s[i][2] = s[i][3] = 0.f;
        #pragma unroll
        for (int k4 = 0; k4 < 16; ++k4) {
            float4 qa[4], kb[4];
            #pragma unroll
            for (int i = 0; i < 4; ++i) qa[i] = *(const float4*)&Qs[tr*4 + i][k4*4];
            #pragma unroll
            for (int j = 0; j < 4; ++j) kb[j] = *(const float4*)&Ks[tc*4 + j][k4*4];
            #pragma unroll
            for (int i = 0; i < 4; ++i)
                #pragma unroll
                for (int j = 0; j < 4; ++j)
                    s[i][j] += qa[i].x*kb[j].x + qa[i].y*kb[j].y
                             + qa[i].z*kb[j].z + qa[i].w*kb[j].w;
        }

        // Online softmax update (row reductions across the 16 lanes sharing tr)
        #pragma unroll
        for (int i = 0; i < 4; ++i) {
            float mt = fmaxf(fmaxf(s[i][0], s[i][1]), fmaxf(s[i][2], s[i][3]));
            mt = fmaxf(mt, __shfl_xor_sync(0xffffffffu, mt, 8, 16));
            mt = fmaxf(mt, __shfl_xor_sync(0xffffffffu, mt, 4, 16));
            mt = fmaxf(mt, __shfl_xor_sync(0xffffffffu, mt, 2, 16));
            mt = fmaxf(mt, __shfl_xor_sync(0xffffffffu, mt, 1, 16));
            float mnew = fmaxf(m_i[i], mt);
            float fac  = __expf(m_i[i] - mnew);
            m_i[i] = mnew;
            float p0 = __expf(s[i][0] - mnew);
            float p1 = __expf(s[i][1] - mnew);
            float p2 = __expf(s[i][2] - mnew);
            float p3 = __expf(s[i][3] - mnew);
            float rs = p0 + p1 + p2 + p3;
            rs += __shfl_xor_sync(0xffffffffu, rs, 8, 16);
            rs += __shfl_xor_sync(0xffffffffu, rs, 4, 16);
            rs += __shfl_xor_sync(0xffffffffu, rs, 2, 16);
            rs += __shfl_xor_sync(0xffffffffu, rs, 1, 16);
            l_i[i] = l_i[i]*fac + rs;
            o[i][0] *= fac; o[i][1] *= fac; o[i][2] *= fac; o[i][3] *= fac;
            *(float4*)&Ps[tr*4 + i][tc*4] = make_float4(p0, p1, p2, p3);
        }
        __syncthreads();

        // O += P @ V
        #pragma unroll
        for (int j4 = 0; j4 < 16; ++j4) {
            float4 pa[4], vb[4];
            #pragma unroll
            for (int i = 0; i < 4; ++i)  pa[i]  = *(const float4*)&Ps[tr*4 + i][j4*4];
            #pragma unroll
            for (int jj = 0; jj < 4; ++jj) vb[jj] = *(const float4*)&Vs[j4*4 + jj][tc*4];
            #pragma unroll
            for (int i = 0; i < 4; ++i) {
                o[i][0] += pa[i].x*vb[0].x + pa[i].y*vb[1].x + pa[i].z*vb[2].x + pa[i].w*vb[3].x;
                o[i][1] += pa[i].x*vb[0].y + pa[i].y*vb[1].y + pa[i].z*vb[2].y + pa[i].w*vb[3].y;
                o[i][2] += pa[i].x*vb[0].z + pa[i].y*vb[1].z + pa[i].z*vb[2].z + pa[i].w*vb[3].z;
                o[i][3] += pa[i].x*vb[0].w + pa[i].y*vb[1].w + pa[i].z*vb[2].w + pa[i].w*vb[3].w;
            }
        }
    }

    // Epilogue: normalize by l and store
    float* og = out + ((size_t)b*SEQ + q0)*HDIM;
    #pragma unroll
    for (int i = 0; i < 4; ++i) {
        float inv = 1.f / l_i[i];
        *(float4*)(og + (size_t)(tr*4 + i)*HDIM + tc*4) =
            make_float4(o[i][0]*inv, o[i][1]*inv, o[i][2]*inv, o[i][3]*inv);
    }
}

extern "C" void kernel_launch(void* const* d_in, const int* in_sizes, int n_in,
                              void* d_out, int out_size)
{
    const float* x  = (const float*)d_in[0];
    const float* Wk = (const float*)d_in[1];
    const float* Wq = (const float*)d_in[2];
    const float* Wv = (const float*)d_in[3];
    float* out = (float*)d_out;

    const int smem = 4 * 64 * 68 * (int)sizeof(float);  // 69632 B
    cudaFuncSetAttribute(attn_kernel, cudaFuncAttributeMaxDynamicSharedMemorySize, smem);

    proj_kernel<<<BT/64, 256>>>(x, Wk, Wq, Wv);
    attn_kernel<<<dim3(SEQ/64, BATCH), 256, smem>>>(out);
}